// round 8
// baseline (speedup 1.0000x reference)
#include <cuda_runtime.h>

#define NBATCH 128
#define NCLS   81
#define NA     8732
#define ABLK   35      // ceil(8732/256)
#define NBLOCKS (ABLK * NBATCH)

// Scratch (device globals — no allocation allowed in kernel_launch)
// Partials transposed: index = blockIdx.x * NBATCH + n  (coalesced for finisher)
__device__ float g_part_ll [NBLOCKS];
__device__ float g_part_all[NBLOCKS];
__device__ float g_part_pos[NBLOCKS];
__device__ int   g_part_cnt[NBLOCKS];
__device__ float g_conrow[NA];          // rare-path staging (GMEM, not SMEM)
__device__ unsigned g_ticket;           // zero-initialized; reset by finisher

// ---------------- block reductions ----------------
__device__ __forceinline__ float blockReduceSumF(float v, float* sh) {
    int lane = threadIdx.x & 31, w = threadIdx.x >> 5;
    #pragma unroll
    for (int o = 16; o > 0; o >>= 1) v += __shfl_down_sync(0xffffffffu, v, o);
    __syncthreads();
    if (lane == 0) sh[w] = v;
    __syncthreads();
    float r = (threadIdx.x < (blockDim.x >> 5)) ? sh[threadIdx.x] : 0.f;
    if (w == 0) {
        #pragma unroll
        for (int o = 16; o > 0; o >>= 1) r += __shfl_down_sync(0xffffffffu, r, o);
        if (lane == 0) sh[0] = r;
    }
    __syncthreads();
    return sh[0];
}

__device__ __forceinline__ int blockReduceSumI(int v, int* sh) {
    int lane = threadIdx.x & 31, w = threadIdx.x >> 5;
    #pragma unroll
    for (int o = 16; o > 0; o >>= 1) v += __shfl_down_sync(0xffffffffu, v, o);
    __syncthreads();
    if (lane == 0) sh[w] = v;
    __syncthreads();
    int r = (threadIdx.x < (blockDim.x >> 5)) ? sh[threadIdx.x] : 0;
    if (w == 0) {
        #pragma unroll
        for (int o = 16; o > 0; o >>= 1) r += __shfl_down_sync(0xffffffffu, r, o);
        if (lane == 0) sh[0] = r;
    }
    __syncthreads();
    return sh[0];
}

// per-anchor CE over 81 classes (identical source order on both call sites)
__device__ __forceinline__ float anchor_ce(const float* __restrict__ base, int g) {
    float m = -1e30f, s = 0.f, xg = 0.f;
    #pragma unroll
    for (int ch = 0; ch < 3; ch++) {
        float x[27];
        #pragma unroll
        for (int i = 0; i < 27; i++)
            x[i] = __ldcs(base + (size_t)(ch * 27 + i) * NA);
        float mc = x[0];
        #pragma unroll
        for (int i = 1; i < 27; i++) mc = fmaxf(mc, x[i]);
        float sc = 0.f;
        #pragma unroll
        for (int i = 0; i < 27; i++) sc += __expf(x[i] - mc);
        #pragma unroll
        for (int i = 0; i < 27; i++)
            xg = (ch * 27 + i == g) ? x[i] : xg;
        float mn = fmaxf(m, mc);
        s = s * __expf(m - mn) + sc * __expf(mc - mn);
        m = mn;
    }
    return m + __logf(s) - xg;
}

// ---- single kernel: CE stream + loc loss + partials; last block finishes ----
__global__ __launch_bounds__(256, 6) void ssd_kernel(
        const float* __restrict__ plabel,
        const int*   __restrict__ glabel,
        const float* __restrict__ ploc,
        const float* __restrict__ gloc,
        const float* __restrict__ dboxes,
        const float* __restrict__ pt2,
        const float* __restrict__ gt2,
        float* __restrict__ out) {
    __shared__ float shf[32];
    __shared__ int   shi[32];
    __shared__ unsigned s_last;
    // finisher scratch (~5 KB; 6 blocks x 5.3 KB well under 228 KB/SM)
    __shared__ float s_loc[NBATCH], s_con[NBATCH];
    __shared__ float s_ll[NBATCH],  s_pos[NBATCH];
    __shared__ int   s_cnt[NBATCH], s_k[NBATCH], s_need[NBATCH];
    __shared__ int   s_eq[256];
    __shared__ unsigned sh_pref;
    __shared__ int      sh_kk;

    const int a = blockIdx.x * blockDim.x + threadIdx.x;
    const int n = blockIdx.y;
    const int tid = threadIdx.x;
    const int TT  = blockDim.x;  // 256

    float con = 0.f, ll = 0.f;
    int   mk  = 0;
    bool  act = (a < NA);

    if (act) {
        int g = glabel[n * NA + a];
        con = anchor_ce(plabel + (size_t)n * NCLS * NA + a, g);
        mk  = (g > 0) ? 1 : 0;

        if (mk) {
            const float* glb = gloc + (size_t)n * 4 * NA;
            const float* plb = ploc + (size_t)n * 4 * NA;
            float dx = dboxes[a],        dy = dboxes[NA + a];
            float dw = dboxes[2*NA + a], dh = dboxes[3*NA + a];
            float v0 = 10.f * __fdividef(glb[a]      - dx, dw);
            float v1 = 10.f * __fdividef(glb[NA + a] - dy, dh);
            float v2 = 5.f * __logf(__fdividef(glb[2*NA + a], dw));
            float v3 = 5.f * __logf(__fdividef(glb[3*NA + a], dh));
            float d, ad;
            d = plb[a]        - v0; ad = fabsf(d); ll += (ad < 1.f) ? 0.5f*d*d : ad - 0.5f;
            d = plb[NA + a]   - v1; ad = fabsf(d); ll += (ad < 1.f) ? 0.5f*d*d : ad - 0.5f;
            d = plb[2*NA + a] - v2; ad = fabsf(d); ll += (ad < 1.f) ? 0.5f*d*d : ad - 0.5f;
            d = plb[3*NA + a] - v3; ad = fabsf(d); ll += (ad < 1.f) ? 0.5f*d*d : ad - 0.5f;
        }
    }

    float v_all = act ? con : 0.f;
    float v_pos = mk  ? con : 0.f;
    float r_ll  = blockReduceSumF(ll,    shf);
    float r_all = blockReduceSumF(v_all, shf);
    float r_pos = blockReduceSumF(v_pos, shf);
    int   r_cnt = blockReduceSumI(mk,    shi);
    if (tid == 0) {
        int p = blockIdx.x * NBATCH + n;   // transposed layout
        g_part_ll [p] = r_ll;
        g_part_all[p] = r_all;
        g_part_pos[p] = r_pos;
        g_part_cnt[p] = r_cnt;
        __threadfence();
        unsigned t = atomicAdd(&g_ticket, 1u);
        s_last = (t == NBLOCKS - 1) ? 1u : 0u;
    }
    __syncthreads();
    if (!s_last) return;

    // =========== finisher (exactly one block reaches here) ===========
    // phase 1: per-row reduction of partials; coalesced (i*NBATCH + tid)
    if (tid < NBATCH) {
        float fll = 0.f, fall = 0.f, fpos = 0.f; int fcnt = 0;
        #pragma unroll 5
        for (int i = 0; i < ABLK; i++) {
            int p = i * NBATCH + tid;
            fll  += g_part_ll [p];
            fall += g_part_all[p];
            fpos += g_part_pos[p];
            fcnt += g_part_cnt[p];
        }
        int k = min(3 * fcnt, NA);
        float rl = 0.f, rc = 0.f;
        int need = 0;
        if (fcnt > 0) {
            if (k >= NA) {
                rl = fll / (float)fcnt;
                rc = (fpos + fall) / (float)fcnt;
            } else {
                need = 1;
            }
        }
        s_loc[tid] = rl;  s_con[tid] = rc;
        s_ll[tid]  = fll; s_pos[tid] = fpos;
        s_cnt[tid] = fcnt; s_k[tid]  = k;
        s_need[tid] = need;
    }
    __syncthreads();

    // phase 2: rare rows needing exact hard-neg select (recompute con row)
    for (int rn = 0; rn < NBATCH; rn++) {
        if (!s_need[rn]) continue;
        for (int aa = tid; aa < NA; aa += TT) {
            int g = glabel[rn * NA + aa];
            g_conrow[aa] = anchor_ce(plabel + (size_t)rn * NCLS * NA + aa, g);
        }
        if (tid == 0) { sh_pref = 0u; sh_kk = s_k[rn]; }
        __syncthreads();
        // k-th largest of con_neg (con>=0 so float bits order-preserving),
        // stable ties by lowest index (matches JAX stable argsort)
        for (int b = 31; b >= 0; b--) {
            unsigned hi   = ~((1u << b) - 1u);
            unsigned cand = sh_pref | (1u << b);
            int c2 = 0;
            for (int aa = tid; aa < NA; aa += TT) {
                unsigned u = (glabel[rn * NA + aa] > 0) ? 0u
                             : __float_as_uint(g_conrow[aa]);
                if ((u & hi) == cand) c2++;
            }
            c2 = blockReduceSumI(c2, shi);
            if (tid == 0) {
                if (c2 >= sh_kk) sh_pref = cand; else sh_kk -= c2;
            }
            __syncthreads();
        }
        unsigned Tv = sh_pref;
        int kk = sh_kk;

        const int chunk = (NA + TT - 1) / TT;
        int lo = tid * chunk, hi2 = min(NA, lo + chunk);
        int eq = 0;
        for (int aa = lo; aa < hi2; aa++) {
            unsigned u = (glabel[rn * NA + aa] > 0) ? 0u
                         : __float_as_uint(g_conrow[aa]);
            if (u == Tv) eq++;
        }
        s_eq[tid] = eq;
        __syncthreads();
        if (tid == 0) {
            int acc = 0;
            for (int t = 0; t < TT; t++) { int c3 = s_eq[t]; s_eq[t] = acc; acc += c3; }
        }
        __syncthreads();
        int rank = s_eq[tid];
        float ssel = 0.f;
        for (int aa = lo; aa < hi2; aa++) {
            unsigned u = (glabel[rn * NA + aa] > 0) ? 0u
                         : __float_as_uint(g_conrow[aa]);
            if (u > Tv) {
                ssel += g_conrow[aa];
            } else if (u == Tv) {
                if (rank < kk) ssel += g_conrow[aa];  // actual con value
                rank++;
            }
        }
        float sum_sel = blockReduceSumF(ssel, shf);
        if (tid == 0) {
            float pf = (float)s_cnt[rn];
            s_loc[rn] = s_ll[rn] / pf;
            s_con[rn] = (s_pos[rn] + sum_sel) / pf;
        }
        __syncthreads();
    }

    // phase 3: means + task2 CE + final scalar; reset ticket for next replay
    float rl = 0.f, rc = 0.f, t2 = 0.f;
    if (tid < NBATCH) {
        rl = s_loc[tid];
        rc = s_con[tid];
        float p0 = pt2[2*tid], p1 = pt2[2*tid + 1];
        float mm = fmaxf(p0, p1);
        float lse = mm + __logf(__expf(p0 - mm) + __expf(p1 - mm));
        t2 = -(gt2[2*tid] * (p0 - lse) + gt2[2*tid + 1] * (p1 - lse));
    }
    float sl = blockReduceSumF(rl, shf);
    float sc = blockReduceSumF(rc, shf);
    float st = blockReduceSumF(t2, shf);
    if (tid == 0) {
        out[0] = 0.5f * ((sl + sc) / (float)NBATCH) + 0.5f * (st / (float)NBATCH);
        g_ticket = 0u;            // reset for next graph replay
        __threadfence();
    }
}

extern "C" void kernel_launch(void* const* d_in, const int* in_sizes, int n_in,
                              void* d_out, int out_size) {
    const float* ploc   = (const float*)d_in[0];
    const float* plabel = (const float*)d_in[1];
    const float* gloc   = (const float*)d_in[2];
    const int*   glabel = (const int*)  d_in[3];
    const float* pt2    = (const float*)d_in[4];
    const float* gt2    = (const float*)d_in[5];
    const float* dboxes = (const float*)d_in[6];

    dim3 g1(ABLK, NBATCH);
    ssd_kernel<<<g1, 256>>>(plabel, glabel, ploc, gloc, dboxes,
                            pt2, gt2, (float*)d_out);
}

// round 9
// speedup vs baseline: 1.1665x; 1.1665x over previous
#include <cuda_runtime.h>

#define NBATCH 128
#define NCLS   81
#define NA     8732
#define ABLK   35      // ceil(8732/256)

// Scratch (device globals — no allocation allowed in kernel_launch)
__device__ float g_part_ll [NBATCH * ABLK];
__device__ float g_part_all[NBATCH * ABLK];
__device__ float g_part_pos[NBATCH * ABLK];
__device__ int   g_part_cnt[NBATCH * ABLK];
__device__ float g_row_loc[NBATCH];
__device__ float g_row_con[NBATCH];

// ---------------- block reductions ----------------
__device__ __forceinline__ float blockReduceSumF(float v, float* sh) {
    int lane = threadIdx.x & 31, w = threadIdx.x >> 5;
    #pragma unroll
    for (int o = 16; o > 0; o >>= 1) v += __shfl_down_sync(0xffffffffu, v, o);
    __syncthreads();
    if (lane == 0) sh[w] = v;
    __syncthreads();
    float r = (threadIdx.x < (blockDim.x >> 5)) ? sh[threadIdx.x] : 0.f;
    if (w == 0) {
        #pragma unroll
        for (int o = 16; o > 0; o >>= 1) r += __shfl_down_sync(0xffffffffu, r, o);
        if (lane == 0) sh[0] = r;
    }
    __syncthreads();
    return sh[0];
}

__device__ __forceinline__ int blockReduceSumI(int v, int* sh) {
    int lane = threadIdx.x & 31, w = threadIdx.x >> 5;
    #pragma unroll
    for (int o = 16; o > 0; o >>= 1) v += __shfl_down_sync(0xffffffffu, v, o);
    __syncthreads();
    if (lane == 0) sh[w] = v;
    __syncthreads();
    int r = (threadIdx.x < (blockDim.x >> 5)) ? sh[threadIdx.x] : 0;
    if (w == 0) {
        #pragma unroll
        for (int o = 16; o > 0; o >>= 1) r += __shfl_down_sync(0xffffffffu, r, o);
        if (lane == 0) sh[0] = r;
    }
    __syncthreads();
    return sh[0];
}

// per-anchor CE over 81 classes (identical source order on both call sites)
__device__ __forceinline__ float anchor_ce(const float* __restrict__ base, int g) {
    float m = -1e30f, s = 0.f, xg = 0.f;
    #pragma unroll
    for (int ch = 0; ch < 3; ch++) {
        float x[27];
        #pragma unroll
        for (int i = 0; i < 27; i++)
            x[i] = __ldcs(base + (size_t)(ch * 27 + i) * NA);
        float mc = x[0];
        #pragma unroll
        for (int i = 1; i < 27; i++) mc = fmaxf(mc, x[i]);
        float sc = 0.f;
        #pragma unroll
        for (int i = 0; i < 27; i++) sc += __expf(x[i] - mc);
        #pragma unroll
        for (int i = 0; i < 27; i++)
            xg = (ch * 27 + i == g) ? x[i] : xg;
        float mn = fmaxf(m, mc);
        s = s * __expf(m - mn) + sc * __expf(mc - mn);
        m = mn;
    }
    return m + __logf(s) - xg;
}

// ---- kernel 1: CE stream + loc loss + per-row partial sums (one pass) ----
__global__ __launch_bounds__(256, 6) void fused_kernel(
        const float* __restrict__ plabel,
        const int*   __restrict__ glabel,
        const float* __restrict__ ploc,
        const float* __restrict__ gloc,
        const float* __restrict__ dboxes) {
    __shared__ float shf[32];
    __shared__ int   shi[32];
    const int a = blockIdx.x * blockDim.x + threadIdx.x;
    const int n = blockIdx.y;

    float con = 0.f, ll = 0.f;
    int   mk  = 0;
    bool  act = (a < NA);

    if (act) {
        int g = glabel[n * NA + a];
        con = anchor_ce(plabel + (size_t)n * NCLS * NA + a, g);
        mk  = (g > 0) ? 1 : 0;

        if (mk) {
            const float* glb = gloc + (size_t)n * 4 * NA;
            const float* plb = ploc + (size_t)n * 4 * NA;
            float dx = dboxes[a],        dy = dboxes[NA + a];
            float dw = dboxes[2*NA + a], dh = dboxes[3*NA + a];
            float v0 = 10.f * __fdividef(glb[a]      - dx, dw);
            float v1 = 10.f * __fdividef(glb[NA + a] - dy, dh);
            float v2 = 5.f * __logf(__fdividef(glb[2*NA + a], dw));
            float v3 = 5.f * __logf(__fdividef(glb[3*NA + a], dh));
            float d, ad;
            d = plb[a]        - v0; ad = fabsf(d); ll += (ad < 1.f) ? 0.5f*d*d : ad - 0.5f;
            d = plb[NA + a]   - v1; ad = fabsf(d); ll += (ad < 1.f) ? 0.5f*d*d : ad - 0.5f;
            d = plb[2*NA + a] - v2; ad = fabsf(d); ll += (ad < 1.f) ? 0.5f*d*d : ad - 0.5f;
            d = plb[3*NA + a] - v3; ad = fabsf(d); ll += (ad < 1.f) ? 0.5f*d*d : ad - 0.5f;
        }
    }

    float v_all = act ? con : 0.f;
    float v_pos = mk  ? con : 0.f;
    float r_ll  = blockReduceSumF(ll,    shf);
    float r_all = blockReduceSumF(v_all, shf);
    float r_pos = blockReduceSumF(v_pos, shf);
    int   r_cnt = blockReduceSumI(mk,    shi);
    if (threadIdx.x == 0) {
        int p = n * ABLK + blockIdx.x;   // row-major: select block n reads contiguously
        g_part_ll [p] = r_ll;
        g_part_all[p] = r_all;
        g_part_pos[p] = r_pos;
        g_part_cnt[p] = r_cnt;
    }
}

// ---- kernel 2: one block per row; fast path is partials-only ----
__global__ void select_kernel(const float* __restrict__ plabel,
                              const int*   __restrict__ glabel) {
    __shared__ float scon[NA];               // rare-path staging only
    __shared__ unsigned char smask[NA];
    __shared__ float shf[32];
    __shared__ int   shi[32];
    __shared__ int   s_eq[256];
    __shared__ unsigned sh_pref;
    __shared__ int      sh_kk;

    const int n   = blockIdx.x;
    const int tid = threadIdx.x;
    const int TT  = blockDim.x;   // 256

    // reduce this row's 35 partials (contiguous, L2-hot)
    float ll = 0.f, all = 0.f, pos = 0.f; int cnt = 0;
    if (tid < ABLK) {
        int p = n * ABLK + tid;
        ll  = g_part_ll [p];
        all = g_part_all[p];
        pos = g_part_pos[p];
        cnt = g_part_cnt[p];
    }
    ll  = blockReduceSumF(ll,  shf);
    all = blockReduceSumF(all, shf);
    pos = blockReduceSumF(pos, shf);
    cnt = blockReduceSumI(cnt, shi);

    float row_loc = 0.f, row_con = 0.f;
    int k = min(3 * cnt, NA);
    if (cnt > 0) {
        float sum_sel;
        if (k >= NA) {
            sum_sel = all;   // all anchors selected as "negatives"
        } else {
            // rare path: recompute con row into SMEM (same op order as fused)
            for (int a = tid; a < NA; a += TT) {
                int g = glabel[n * NA + a];
                scon[a]  = anchor_ce(plabel + (size_t)n * NCLS * NA + a, g);
                smask[a] = (g > 0) ? 1 : 0;
            }
            if (tid == 0) { sh_pref = 0u; sh_kk = k; }
            __syncthreads();
            // k-th largest of con_neg (con>=0 so float bits order-preserving),
            // stable ties by lowest index (matches JAX stable argsort)
            for (int b = 31; b >= 0; b--) {
                unsigned hi   = ~((1u << b) - 1u);
                unsigned cand = sh_pref | (1u << b);
                int c2 = 0;
                for (int a = tid; a < NA; a += TT) {
                    unsigned u = smask[a] ? 0u : __float_as_uint(scon[a]);
                    if ((u & hi) == cand) c2++;
                }
                c2 = blockReduceSumI(c2, shi);
                if (tid == 0) {
                    if (c2 >= sh_kk) sh_pref = cand; else sh_kk -= c2;
                }
                __syncthreads();
            }
            unsigned Tv = sh_pref;
            int kk = sh_kk;

            const int chunk = (NA + TT - 1) / TT;
            int lo = tid * chunk, hi2 = min(NA, lo + chunk);
            int eq = 0;
            for (int a = lo; a < hi2; a++) {
                unsigned u = smask[a] ? 0u : __float_as_uint(scon[a]);
                if (u == Tv) eq++;
            }
            s_eq[tid] = eq;
            __syncthreads();
            if (tid == 0) {
                int acc = 0;
                for (int t = 0; t < TT; t++) { int c3 = s_eq[t]; s_eq[t] = acc; acc += c3; }
            }
            __syncthreads();
            int rank = s_eq[tid];
            float ssel = 0.f;
            for (int a = lo; a < hi2; a++) {
                unsigned u = smask[a] ? 0u : __float_as_uint(scon[a]);
                if (u > Tv) {
                    ssel += scon[a];
                } else if (u == Tv) {
                    if (rank < kk) ssel += scon[a];  // actual con value
                    rank++;
                }
            }
            sum_sel = blockReduceSumF(ssel, shf);
        }
        float pf = (float)cnt;
        row_loc = ll / pf;
        row_con = (pos + sum_sel) / pf;
    }
    if (tid == 0) { g_row_loc[n] = row_loc; g_row_con[n] = row_con; }
}

// ---- kernel 3: means + task2 CE + final scalar ----
__global__ void final_kernel(const float* __restrict__ pt2,
                             const float* __restrict__ gt2,
                             float* __restrict__ out) {
    __shared__ float shf[32];
    int n = threadIdx.x;  // 128 threads
    float rl = g_row_loc[n], rc = g_row_con[n];
    float p0 = pt2[2*n], p1 = pt2[2*n + 1];
    float mm = fmaxf(p0, p1);
    float lse = mm + __logf(__expf(p0 - mm) + __expf(p1 - mm));
    float t2 = -(gt2[2*n] * (p0 - lse) + gt2[2*n + 1] * (p1 - lse));
    float sl = blockReduceSumF(rl, shf);
    float sc = blockReduceSumF(rc, shf);
    float st = blockReduceSumF(t2, shf);
    if (n == 0)
        out[0] = 0.5f * ((sl + sc) / (float)NBATCH) + 0.5f * (st / (float)NBATCH);
}

extern "C" void kernel_launch(void* const* d_in, const int* in_sizes, int n_in,
                              void* d_out, int out_size) {
    const float* ploc   = (const float*)d_in[0];
    const float* plabel = (const float*)d_in[1];
    const float* gloc   = (const float*)d_in[2];
    const int*   glabel = (const int*)  d_in[3];
    const float* pt2    = (const float*)d_in[4];
    const float* gt2    = (const float*)d_in[5];
    const float* dboxes = (const float*)d_in[6];

    dim3 g1(ABLK, NBATCH);
    fused_kernel<<<g1, 256>>>(plabel, glabel, ploc, gloc, dboxes);
    select_kernel<<<NBATCH, 256>>>(plabel, glabel);
    final_kernel<<<1, 128>>>(pt2, gt2, (float*)d_out);
}

// round 10
// speedup vs baseline: 1.1753x; 1.0076x over previous
#include <cuda_runtime.h>

#define NBATCH 128
#define NCLS   81
#define NA     8732
#define ABLK   35      // ceil(8732/256)

// Scratch (device globals — no allocation allowed in kernel_launch)
__device__ float g_part_ll [NBATCH * ABLK];
__device__ float g_part_all[NBATCH * ABLK];
__device__ float g_part_pos[NBATCH * ABLK];
__device__ int   g_part_cnt[NBATCH * ABLK];
__device__ float g_row_loc[NBATCH];
__device__ float g_row_con[NBATCH];

// ---------------- block reductions ----------------
__device__ __forceinline__ float blockReduceSumF(float v, float* sh) {
    int lane = threadIdx.x & 31, w = threadIdx.x >> 5;
    #pragma unroll
    for (int o = 16; o > 0; o >>= 1) v += __shfl_down_sync(0xffffffffu, v, o);
    __syncthreads();
    if (lane == 0) sh[w] = v;
    __syncthreads();
    float r = (threadIdx.x < (blockDim.x >> 5)) ? sh[threadIdx.x] : 0.f;
    if (w == 0) {
        #pragma unroll
        for (int o = 16; o > 0; o >>= 1) r += __shfl_down_sync(0xffffffffu, r, o);
        if (lane == 0) sh[0] = r;
    }
    __syncthreads();
    return sh[0];
}

__device__ __forceinline__ int blockReduceSumI(int v, int* sh) {
    int lane = threadIdx.x & 31, w = threadIdx.x >> 5;
    #pragma unroll
    for (int o = 16; o > 0; o >>= 1) v += __shfl_down_sync(0xffffffffu, v, o);
    __syncthreads();
    if (lane == 0) sh[w] = v;
    __syncthreads();
    int r = (threadIdx.x < (blockDim.x >> 5)) ? sh[threadIdx.x] : 0;
    if (w == 0) {
        #pragma unroll
        for (int o = 16; o > 0; o >>= 1) r += __shfl_down_sync(0xffffffffu, r, o);
        if (lane == 0) sh[0] = r;
    }
    __syncthreads();
    return sh[0];
}

// per-anchor CE over 81 classes (identical source order on both call sites).
// x_g fetched by direct load (bit-identical to in-register selection; the
// line is L1/L2-hot from the streaming pass) — saves 162 ALU instrs/anchor.
__device__ __forceinline__ float anchor_ce(const float* __restrict__ base, int g) {
    float m = -1e30f, s = 0.f;
    #pragma unroll
    for (int ch = 0; ch < 3; ch++) {
        float x[27];
        #pragma unroll
        for (int i = 0; i < 27; i++)
            x[i] = __ldcs(base + (size_t)(ch * 27 + i) * NA);
        float mc = x[0];
        #pragma unroll
        for (int i = 1; i < 27; i++) mc = fmaxf(mc, x[i]);
        float sc = 0.f;
        #pragma unroll
        for (int i = 0; i < 27; i++) sc += __expf(x[i] - mc);
        float mn = fmaxf(m, mc);
        s = s * __expf(m - mn) + sc * __expf(mc - mn);
        m = mn;
    }
    float xg = __ldca(base + (size_t)g * NA);
    return m + __logf(s) - xg;
}

// ---- kernel 1: CE stream + loc loss + per-row partial sums (one pass) ----
__global__ __launch_bounds__(256, 6) void fused_kernel(
        const float* __restrict__ plabel,
        const int*   __restrict__ glabel,
        const float* __restrict__ ploc,
        const float* __restrict__ gloc,
        const float* __restrict__ dboxes) {
    __shared__ float shf[32];
    __shared__ int   shi[32];
    const int a = blockIdx.x * blockDim.x + threadIdx.x;
    const int n = blockIdx.y;

    float con = 0.f, ll = 0.f;
    int   mk  = 0;
    bool  act = (a < NA);

    if (act) {
        int g = glabel[n * NA + a];
        con = anchor_ce(plabel + (size_t)n * NCLS * NA + a, g);
        mk  = (g > 0) ? 1 : 0;

        if (mk) {
            const float* glb = gloc + (size_t)n * 4 * NA;
            const float* plb = ploc + (size_t)n * 4 * NA;
            float dx = dboxes[a],        dy = dboxes[NA + a];
            float dw = dboxes[2*NA + a], dh = dboxes[3*NA + a];
            float v0 = 10.f * __fdividef(__ldcs(glb + a)      - dx, dw);
            float v1 = 10.f * __fdividef(__ldcs(glb + NA + a) - dy, dh);
            float v2 = 5.f * __logf(__fdividef(__ldcs(glb + 2*NA + a), dw));
            float v3 = 5.f * __logf(__fdividef(__ldcs(glb + 3*NA + a), dh));
            float d, ad;
            d = __ldcs(plb + a)        - v0; ad = fabsf(d); ll += (ad < 1.f) ? 0.5f*d*d : ad - 0.5f;
            d = __ldcs(plb + NA + a)   - v1; ad = fabsf(d); ll += (ad < 1.f) ? 0.5f*d*d : ad - 0.5f;
            d = __ldcs(plb + 2*NA + a) - v2; ad = fabsf(d); ll += (ad < 1.f) ? 0.5f*d*d : ad - 0.5f;
            d = __ldcs(plb + 3*NA + a) - v3; ad = fabsf(d); ll += (ad < 1.f) ? 0.5f*d*d : ad - 0.5f;
        }
    }

    float v_all = act ? con : 0.f;
    float v_pos = mk  ? con : 0.f;
    float r_ll  = blockReduceSumF(ll,    shf);
    float r_all = blockReduceSumF(v_all, shf);
    float r_pos = blockReduceSumF(v_pos, shf);
    int   r_cnt = blockReduceSumI(mk,    shi);
    if (threadIdx.x == 0) {
        int p = n * ABLK + blockIdx.x;   // row-major: select block n reads contiguously
        g_part_ll [p] = r_ll;
        g_part_all[p] = r_all;
        g_part_pos[p] = r_pos;
        g_part_cnt[p] = r_cnt;
    }
}

// ---- kernel 2: one block per row; fast path is partials-only ----
__global__ void select_kernel(const float* __restrict__ plabel,
                              const int*   __restrict__ glabel) {
    __shared__ float scon[NA];               // rare-path staging only
    __shared__ unsigned char smask[NA];
    __shared__ float shf[32];
    __shared__ int   shi[32];
    __shared__ int   s_eq[256];
    __shared__ unsigned sh_pref;
    __shared__ int      sh_kk;

    const int n   = blockIdx.x;
    const int tid = threadIdx.x;
    const int TT  = blockDim.x;   // 256

    // reduce this row's 35 partials (contiguous, L2-hot)
    float ll = 0.f, all = 0.f, pos = 0.f; int cnt = 0;
    if (tid < ABLK) {
        int p = n * ABLK + tid;
        ll  = g_part_ll [p];
        all = g_part_all[p];
        pos = g_part_pos[p];
        cnt = g_part_cnt[p];
    }
    ll  = blockReduceSumF(ll,  shf);
    all = blockReduceSumF(all, shf);
    pos = blockReduceSumF(pos, shf);
    cnt = blockReduceSumI(cnt, shi);

    float row_loc = 0.f, row_con = 0.f;
    int k = min(3 * cnt, NA);
    if (cnt > 0) {
        float sum_sel;
        if (k >= NA) {
            sum_sel = all;   // all anchors selected as "negatives"
        } else {
            // rare path: recompute con row into SMEM (same op order as fused)
            for (int a = tid; a < NA; a += TT) {
                int g = glabel[n * NA + a];
                scon[a]  = anchor_ce(plabel + (size_t)n * NCLS * NA + a, g);
                smask[a] = (g > 0) ? 1 : 0;
            }
            if (tid == 0) { sh_pref = 0u; sh_kk = k; }
            __syncthreads();
            // k-th largest of con_neg (con>=0 so float bits order-preserving),
            // stable ties by lowest index (matches JAX stable argsort)
            for (int b = 31; b >= 0; b--) {
                unsigned hi   = ~((1u << b) - 1u);
                unsigned cand = sh_pref | (1u << b);
                int c2 = 0;
                for (int a = tid; a < NA; a += TT) {
                    unsigned u = smask[a] ? 0u : __float_as_uint(scon[a]);
                    if ((u & hi) == cand) c2++;
                }
                c2 = blockReduceSumI(c2, shi);
                if (tid == 0) {
                    if (c2 >= sh_kk) sh_pref = cand; else sh_kk -= c2;
                }
                __syncthreads();
            }
            unsigned Tv = sh_pref;
            int kk = sh_kk;

            const int chunk = (NA + TT - 1) / TT;
            int lo = tid * chunk, hi2 = min(NA, lo + chunk);
            int eq = 0;
            for (int a = lo; a < hi2; a++) {
                unsigned u = smask[a] ? 0u : __float_as_uint(scon[a]);
                if (u == Tv) eq++;
            }
            s_eq[tid] = eq;
            __syncthreads();
            if (tid == 0) {
                int acc = 0;
                for (int t = 0; t < TT; t++) { int c3 = s_eq[t]; s_eq[t] = acc; acc += c3; }
            }
            __syncthreads();
            int rank = s_eq[tid];
            float ssel = 0.f;
            for (int a = lo; a < hi2; a++) {
                unsigned u = smask[a] ? 0u : __float_as_uint(scon[a]);
                if (u > Tv) {
                    ssel += scon[a];
                } else if (u == Tv) {
                    if (rank < kk) ssel += scon[a];  // actual con value
                    rank++;
                }
            }
            sum_sel = blockReduceSumF(ssel, shf);
        }
        float pf = (float)cnt;
        row_loc = ll / pf;
        row_con = (pos + sum_sel) / pf;
    }
    if (tid == 0) { g_row_loc[n] = row_loc; g_row_con[n] = row_con; }
}

// ---- kernel 3: means + task2 CE + final scalar ----
__global__ void final_kernel(const float* __restrict__ pt2,
                             const float* __restrict__ gt2,
                             float* __restrict__ out) {
    __shared__ float shf[32];
    int n = threadIdx.x;  // 128 threads
    float rl = g_row_loc[n], rc = g_row_con[n];
    float p0 = pt2[2*n], p1 = pt2[2*n + 1];
    float mm = fmaxf(p0, p1);
    float lse = mm + __logf(__expf(p0 - mm) + __expf(p1 - mm));
    float t2 = -(gt2[2*n] * (p0 - lse) + gt2[2*n + 1] * (p1 - lse));
    float sl = blockReduceSumF(rl, shf);
    float sc = blockReduceSumF(rc, shf);
    float st = blockReduceSumF(t2, shf);
    if (n == 0)
        out[0] = 0.5f * ((sl + sc) / (float)NBATCH) + 0.5f * (st / (float)NBATCH);
}

extern "C" void kernel_launch(void* const* d_in, const int* in_sizes, int n_in,
                              void* d_out, int out_size) {
    const float* ploc   = (const float*)d_in[0];
    const float* plabel = (const float*)d_in[1];
    const float* gloc   = (const float*)d_in[2];
    const int*   glabel = (const int*)  d_in[3];
    const float* pt2    = (const float*)d_in[4];
    const float* gt2    = (const float*)d_in[5];
    const float* dboxes = (const float*)d_in[6];

    dim3 g1(ABLK, NBATCH);
    fused_kernel<<<g1, 256>>>(plabel, glabel, ploc, gloc, dboxes);
    select_kernel<<<NBATCH, 256>>>(plabel, glabel);
    final_kernel<<<1, 128>>>(pt2, gt2, (float*)d_out);
}